// round 17
// baseline (speedup 1.0000x reference)
#include <cuda_runtime.h>
#include <cuda_fp16.h>
#include <cstdint>
#include <mma.h>
#include <math.h>
#include <float.h>

using namespace nvcuda;

#define SEQ   2048
#define HID   4096
#define NH    32
#define HD    128
#define QKVN  12288   // 3*HID

#define NPERS 304     // persistent CTAs: 2 per SM x 152 SMs (GB300)

// ---------------- scratch (no cudaMalloc allowed) ----------------
__device__ __half g_attn16[SEQ * HID];
__device__ __half g_hs16[SEQ * HID];
__device__ __half g_wq16[(size_t)HID * QKVN];
__device__ __half g_wo16[(size_t)HID * HID];
__device__ __half g_qk16[SEQ * 2 * HID];
__device__ __half g_vT[(size_t)NH * HD * SEQ];
__device__ float2 g_tab[SEQ * 64];

// ---------------- cp.async helpers ----------------
__device__ __forceinline__ void cp_async16(void* smem_dst, const void* gsrc) {
    unsigned s = (unsigned)__cvta_generic_to_shared(smem_dst);
    asm volatile("cp.async.cg.shared.global [%0], [%1], 16;\n" :: "r"(s), "l"(gsrc));
}
__device__ __forceinline__ void cp_commit() {
    asm volatile("cp.async.commit_group;\n");
}
template <int N> __device__ __forceinline__ void cp_wait() {
    asm volatile("cp.async.wait_group %0;\n" :: "n"(N));
}

__device__ __forceinline__ constexpr int p16(int h) {
    return (h < 8) ? ((h >> 1) << 2) + (h & 1)
                   : (((h - 8) >> 1) << 2) + 2 + (h & 1);
}
__device__ __forceinline__ int permd(int d) {
    return (d & ~15) + p16(d & 15);
}

// ---------------- merged pre-pass: cvt(Wqkv) + cvt(hs) + rope table ------
#define WQ_BLOCKS 49152
#define HS_BLOCKS 8192
#define TAB_BLOCKS 512
__global__ __launch_bounds__(256)
void pre_kernel(const float* __restrict__ Wqkv, __half* __restrict__ wq16,
                const float* __restrict__ hs, __half* __restrict__ hs16,
                float2* __restrict__ tab) {
    int b = blockIdx.x;
    if (b < WQ_BLOCKS) {
        size_t i = (size_t)b * 256 + threadIdx.x;
        float4 v = ((const float4*)Wqkv)[i];
        __half2 h0 = __floats2half2_rn(v.x, v.y);
        __half2 h1 = __floats2half2_rn(v.z, v.w);
        uint2 pk;
        pk.x = *(unsigned*)&h0;
        pk.y = *(unsigned*)&h1;
        ((uint2*)wq16)[i] = pk;
    } else if (b < WQ_BLOCKS + HS_BLOCKS) {
        size_t i = (size_t)(b - WQ_BLOCKS) * 256 + threadIdx.x;
        float4 v = ((const float4*)hs)[i];
        __half2 h0 = __floats2half2_rn(v.x, v.y);
        __half2 h1 = __floats2half2_rn(v.z, v.w);
        uint2 pk;
        pk.x = *(unsigned*)&h0;
        pk.y = *(unsigned*)&h1;
        ((uint2*)hs16)[i] = pk;
    } else {
        int idx = (b - WQ_BLOCKS - HS_BLOCKS) * 256 + threadIdx.x;
        int s = idx >> 6, i = idx & 63;
        float invf = expf(-0.14391156831212787f * (float)i);
        float f = (float)s * invf;
        tab[idx] = make_float2(cosf(f), sinf(f));
    }
}

// ================= fp16 GEMM core (128x128x64, 4 warps 2x2, 64x64/warp) ==
#define BM 128
#define BN 128
#define BK 64
#define A_LD 72
#define B_LD 136
#define STG 3
#define GEMM_SMEM_BYTES (STG * (BM * A_LD + BK * B_LD) * 2)   // 107520

// ---- persistent QKV GEMM with FUSED rope + V-transpose epilogue ----
__global__ __launch_bounds__(128, 2)
void gemm_qkv_fused(const __half* __restrict__ A, const __half* __restrict__ B,
                    const float* __restrict__ bias,
                    __half* __restrict__ qk16, __half* __restrict__ vT,
                    const float2* __restrict__ tab) {
    extern __shared__ __half gsm[];
    __half* Asm = gsm;
    __half* Bsm = gsm + STG * BM * A_LD;
    const int K = HID, N = QKVN;
    const int NT = (SEQ / BM) * (QKVN / BN);   // 1536

    const int tid  = threadIdx.x;
    const int wid  = tid >> 5;
    const int warp_m = (wid & 1) * 64;
    const int warp_n = (wid >> 1) * 64;

    for (int t0 = blockIdx.x; t0 < NT; t0 += gridDim.x) {
        const int by = t0 & 15;    // M tile (fast)
        const int bx = t0 >> 4;    // N tile

        const __half* Ag = A + (size_t)(by * BM) * K;
        const __half* Bg = B + bx * BN;

        auto load_stage = [&](int s, int k0) {
            __half* As_s = Asm + s * BM * A_LD;
            __half* Bs_s = Bsm + s * BK * B_LD;
#pragma unroll
            for (int p = 0; p < 8; p++) {
                int idx = tid + p * 128;
                int ar = idx >> 3, ack = (idx & 7) * 8;
                cp_async16(&As_s[ar * A_LD + ack], Ag + (size_t)ar * K + k0 + ack);
            }
#pragma unroll
            for (int p = 0; p < 8; p++) {
                int idx = tid + p * 128;
                int br = idx >> 4, bck = (idx & 15) * 8;
                cp_async16(&Bs_s[br * B_LD + bck], Bg + (size_t)(k0 + br) * N + bck);
            }
        };

        wmma::fragment<wmma::accumulator, 16, 16, 16, float> acc[4][4];
#pragma unroll
        for (int i = 0; i < 4; i++)
#pragma unroll
            for (int j = 0; j < 4; j++) wmma::fill_fragment(acc[i][j], 0.0f);

        const int T = K / BK;
        load_stage(0, 0);  cp_commit();
        load_stage(1, BK); cp_commit();

        for (int t = 0; t < T; t++) {
            cp_wait<1>();
            __syncthreads();
            if (t + 2 < T) load_stage((t + 2) % 3, (t + 2) * BK);
            cp_commit();

            const int cur = t % 3;
            const __half* At = Asm + cur * BM * A_LD;
            const __half* Bt = Bsm + cur * BK * B_LD;
#pragma unroll
            for (int kk = 0; kk < BK; kk += 16) {
                wmma::fragment<wmma::matrix_a, 16, 16, 16, __half, wmma::row_major> af[4];
#pragma unroll
                for (int i = 0; i < 4; i++)
                    wmma::load_matrix_sync(af[i], At + (warp_m + i * 16) * A_LD + kk, A_LD);
                wmma::fragment<wmma::matrix_b, 16, 16, 16, __half, wmma::row_major> bf[2];
                wmma::load_matrix_sync(bf[0], Bt + kk * B_LD + warp_n, B_LD);
#pragma unroll
                for (int j = 0; j < 4; j++) {
                    if (j < 3)
                        wmma::load_matrix_sync(bf[(j + 1) & 1],
                                               Bt + kk * B_LD + warp_n + (j + 1) * 16, B_LD);
#pragma unroll
                    for (int i = 0; i < 4; i++)
                        wmma::mma_sync(acc[i][j], af[i], bf[j & 1], acc[i][j]);
                }
            }
        }
        __syncthreads();

        // ---- fused epilogue: stage full 128x128 tile fp32 in smem ----
        float* buf = (float*)gsm;   // [128][132] (aliases pipeline stages)
#pragma unroll
        for (int i = 0; i < 4; i++)
#pragma unroll
            for (int j = 0; j < 4; j++)
                wmma::store_matrix_sync(buf + (warp_m + i * 16) * 132 + warp_n + j * 16,
                                        acc[i][j], 132, wmma::mem_row_major);
        __syncthreads();

        if (bx < 64) {
            const bool isQ = (bx < 32);
            const int h = isQ ? bx : bx - 32;
            const float scale = 0.08838834764831843f;
            int dp  = tid & 63;
            int s0h = tid >> 6;
            const float b1 = bias[bx * 128 + dp];
            const float b2 = bias[bx * 128 + dp + 64];
            const int pd1 = permd(dp), pd2 = permd(dp + 64);
            __half* base = qk16 + (isQ ? 0 : HID) + h * HD;
            for (int s = s0h; s < 128; s += 2) {
                float f1 = buf[s * 132 + dp] + b1;
                float f2 = buf[s * 132 + dp + 64] + b2;
                int row = by * 128 + s;
                float2 cs = tab[row * 64 + dp];
                float o1 = f1 * cs.x - f2 * cs.y;
                float o2 = f2 * cs.x + f1 * cs.y;
                if (isQ) { o1 *= scale; o2 *= scale; }
                __half* dst = base + (size_t)row * 2 * HID;
                dst[pd1] = __float2half(o1);
                dst[pd2] = __float2half(o2);
            }
        } else {
            const int h = bx - 64;
            const int d = tid;
            const float bv = bias[bx * 128 + d];
            __half* dst = vT + (size_t)(h * HD + d) * SEQ + by * 128;
            for (int sb = 0; sb < 128; sb += 16) {
                __align__(16) __half hb[16];
#pragma unroll
                for (int j = 0; j < 16; j++)
                    hb[p16(j)] = __float2half(buf[(sb + j) * 132 + d] + bv);
                *(uint4*)(dst + sb)     = *(uint4*)&hb[0];
                *(uint4*)(dst + sb + 8) = *(uint4*)&hb[8];
            }
        }
        __syncthreads();   // protect buf before next tile's prologue
    }
}

// ---- persistent fp16 GEMM + bias (fp32 out) for the O-projection ----
__global__ __launch_bounds__(128, 2)
void gemm_f16_bias(const __half* __restrict__ A, const __half* __restrict__ B,
                   const float* __restrict__ bias, float* __restrict__ C,
                   int K, int N) {
    extern __shared__ __half gsm[];
    __half* Asm = gsm;
    __half* Bsm = gsm + STG * BM * A_LD;
    const int NT = (SEQ / BM) * (N / BN);

    const int tid  = threadIdx.x;
    const int wid  = tid >> 5;
    const int lane = tid & 31;
    const int warp_m = (wid & 1) * 64;
    const int warp_n = (wid >> 1) * 64;

    for (int t0 = blockIdx.x; t0 < NT; t0 += gridDim.x) {
        const int by = t0 & 15;
        const int bx = t0 >> 4;

        const __half* Ag = A + (size_t)(by * BM) * K;
        const __half* Bg = B + bx * BN;

        auto load_stage = [&](int s, int k0) {
            __half* As_s = Asm + s * BM * A_LD;
            __half* Bs_s = Bsm + s * BK * B_LD;
#pragma unroll
            for (int p = 0; p < 8; p++) {
                int idx = tid + p * 128;
                int ar = idx >> 3, ack = (idx & 7) * 8;
                cp_async16(&As_s[ar * A_LD + ack], Ag + (size_t)ar * K + k0 + ack);
            }
#pragma unroll
            for (int p = 0; p < 8; p++) {
                int idx = tid + p * 128;
                int br = idx >> 4, bck = (idx & 15) * 8;
                cp_async16(&Bs_s[br * B_LD + bck], Bg + (size_t)(k0 + br) * N + bck);
            }
        };

        wmma::fragment<wmma::accumulator, 16, 16, 16, float> acc[4][4];
#pragma unroll
        for (int i = 0; i < 4; i++)
#pragma unroll
            for (int j = 0; j < 4; j++) wmma::fill_fragment(acc[i][j], 0.0f);

        const int T = K / BK;
        load_stage(0, 0);  cp_commit();
        load_stage(1, BK); cp_commit();

        for (int t = 0; t < T; t++) {
            cp_wait<1>();
            __syncthreads();
            if (t + 2 < T) load_stage((t + 2) % 3, (t + 2) * BK);
            cp_commit();

            const int cur = t % 3;
            const __half* At = Asm + cur * BM * A_LD;
            const __half* Bt = Bsm + cur * BK * B_LD;
#pragma unroll
            for (int kk = 0; kk < BK; kk += 16) {
                wmma::fragment<wmma::matrix_a, 16, 16, 16, __half, wmma::row_major> af[4];
#pragma unroll
                for (int i = 0; i < 4; i++)
                    wmma::load_matrix_sync(af[i], At + (warp_m + i * 16) * A_LD + kk, A_LD);
                wmma::fragment<wmma::matrix_b, 16, 16, 16, __half, wmma::row_major> bf[2];
                wmma::load_matrix_sync(bf[0], Bt + kk * B_LD + warp_n, B_LD);
#pragma unroll
                for (int j = 0; j < 4; j++) {
                    if (j < 3)
                        wmma::load_matrix_sync(bf[(j + 1) & 1],
                                               Bt + kk * B_LD + warp_n + (j + 1) * 16, B_LD);
#pragma unroll
                    for (int i = 0; i < 4; i++)
                        wmma::mma_sync(acc[i][j], af[i], bf[j & 1], acc[i][j]);
                }
            }
        }
        __syncthreads();

        float* epi = (float*)gsm + wid * 256;
#pragma unroll
        for (int i = 0; i < 4; i++) {
#pragma unroll
            for (int j = 0; j < 4; j++) {
                wmma::store_matrix_sync(epi, acc[i][j], 16, wmma::mem_row_major);
                __syncwarp();
                int r = lane >> 1;
                int c = (lane & 1) * 8;
                int grow = by * BM + warp_m + i * 16 + r;
                int gcol = bx * BN + warp_n + j * 16 + c;
                float4 v0 = *(float4*)&epi[r * 16 + c];
                float4 v1 = *(float4*)&epi[r * 16 + c + 4];
                const float* bp = bias + gcol;
                v0.x += bp[0]; v0.y += bp[1]; v0.z += bp[2]; v0.w += bp[3];
                v1.x += bp[4]; v1.y += bp[5]; v1.z += bp[6]; v1.w += bp[7];
                float* cp = C + (size_t)grow * N + gcol;
                *(float4*)cp = v0;
                *(float4*)(cp + 4) = v1;
                __syncwarp();
            }
        }
        __syncthreads();   // protect epi region before next tile's prologue
    }
}

// ================== fused flash attention (fp16 m16n8k16, register P) ====
#define KT 32
#define QK_LDH 144
#define VT_LDH 48
#define SM_Q 0
#define SM_K (128 * QK_LDH)
#define SM_V (SM_K + 2 * KT * QK_LDH)
#define FA_SMEM_HALVES (SM_V + 2 * HD * VT_LDH)
#define FA_SMEM_BYTES (FA_SMEM_HALVES * 2)   // 79872

__device__ __forceinline__ void mma_f16(float* d, unsigned a0, unsigned a1,
                                        unsigned a2, unsigned a3,
                                        unsigned b0, unsigned b1) {
    asm volatile(
        "mma.sync.aligned.m16n8k16.row.col.f32.f16.f16.f32 "
        "{%0,%1,%2,%3}, {%4,%5,%6,%7}, {%8,%9}, {%0,%1,%2,%3};\n"
        : "+f"(d[0]), "+f"(d[1]), "+f"(d[2]), "+f"(d[3])
        : "r"(a0), "r"(a1), "r"(a2), "r"(a3), "r"(b0), "r"(b1));
}
__device__ __forceinline__ unsigned packh2(float a, float b) {
    __half2 h = __floats2half2_rn(a, b);
    return *(unsigned*)&h;
}

__global__ __launch_bounds__(256, 2)
void flash_kernel(const __half* __restrict__ qk16, const __half* __restrict__ vT,
                  __half* __restrict__ attn,
                  const float* __restrict__ Wo, __half* __restrict__ wo16) {
    extern __shared__ __half smh[];
    const int id = blockIdx.x;
    const int by = 15 - (id >> 5);
    const int h  = id & 31;
    const int tid  = threadIdx.x;
    const int wid  = tid >> 5;
    const int lane = tid & 31;
    const int g = lane >> 2;
    const int c = lane & 3;

    __half* Qs = smh + SM_Q;
    __half* Ks = smh + SM_K;
    __half* Vs = smh + SM_V;

    const __half* Qg = qk16 + h * HD;
    const __half* Kg = qk16 + HID + h * HD;
    const __half* Vg = vT + (size_t)h * HD * SEQ;

    const int ktmax = 4 * by + 4;

    for (int i = tid; i < 512; i += 256) {
        int r = i >> 4, ch = (i & 15) * 8;
        cp_async16(&Ks[r * QK_LDH + ch], Kg + (size_t)r * 2 * HID + ch);
    }
    for (int i = tid; i < 512; i += 256) {
        int r = i >> 2, ch = (i & 3) * 8;
        cp_async16(&Vs[r * VT_LDH + ch], Vg + (size_t)r * SEQ + ch);
    }
    for (int i = tid; i < 128 * 16; i += 256) {
        int r = i >> 4, ch = (i & 15) * 8;
        cp_async16(&Qs[r * QK_LDH + ch],
                   Qg + (size_t)(by * 128 + r) * 2 * HID + ch);
    }
    cp_commit();

    float o[16][4];
#pragma unroll
    for (int i = 0; i < 16; i++)
#pragma unroll
        for (int j = 0; j < 4; j++) o[i][j] = 0.0f;
    float m0 = -1e30f, m1 = -1e30f, l0 = 0.0f, l1 = 0.0f;

    const int row0 = by * 128 + wid * 16 + g;
    const int row1 = row0 + 8;

    for (int kt = 0; kt < ktmax; kt++) {
        cp_wait<0>();
        __syncthreads();
        if (kt + 1 < ktmax) {
            const int nb   = (kt + 1) & 1;
            const int key0 = (kt + 1) * KT;
            for (int i = tid; i < 512; i += 256) {
                int r = i >> 4, ch = (i & 15) * 8;
                cp_async16(&Ks[nb * KT * QK_LDH + r * QK_LDH + ch],
                           Kg + (size_t)(key0 + r) * 2 * HID + ch);
            }
            for (int i = tid; i < 512; i += 256) {
                int r = i >> 2, ch = (i & 3) * 8;
                cp_async16(&Vs[nb * HD * VT_LDH + r * VT_LDH + ch],
                           Vg + (size_t)r * SEQ + key0 + ch);
            }
        }
        cp_commit();

        const __half* Kbuf = Ks + (kt & 1) * KT * QK_LDH;
        const __half* Vbuf = Vs + (kt & 1) * HD * VT_LDH;
        const int key0 = kt * KT;

        float s[4][4];
#pragma unroll
        for (int i = 0; i < 4; i++)
#pragma unroll
            for (int j = 0; j < 4; j++) s[i][j] = 0.0f;

        const __half* Qr0 = Qs + (wid * 16 + g) * QK_LDH;
        const __half* Qr1 = Qr0 + 8 * QK_LDH;
#pragma unroll
        for (int ks = 0; ks < 8; ks++) {
            uint2 a02 = *(const uint2*)(Qr0 + ks * 16 + 4 * c);
            uint2 a13 = *(const uint2*)(Qr1 + ks * 16 + 4 * c);
#pragma unroll
            for (int nt = 0; nt < 4; nt++) {
                uint2 b = *(const uint2*)(Kbuf + (nt * 8 + g) * QK_LDH + ks * 16 + 4 * c);
                mma_f16(s[nt], a02.x, a13.x, a02.y, a13.y, b.x, b.y);
            }
        }

        if (kt >= 4 * by) {
#pragma unroll
            for (int nt = 0; nt < 4; nt++) {
                int col = key0 + nt * 8 + 2 * c;
                if (col     > row0) s[nt][0] = -1e30f;
                if (col + 1 > row0) s[nt][1] = -1e30f;
                if (col     > row1) s[nt][2] = -1e30f;
                if (col + 1 > row1) s[nt][3] = -1e30f;
            }
        }

        float tm0 = -1e30f, tm1 = -1e30f;
#pragma unroll
        for (int nt = 0; nt < 4; nt++) {
            tm0 = fmaxf(tm0, fmaxf(s[nt][0], s[nt][1]));
            tm1 = fmaxf(tm1, fmaxf(s[nt][2], s[nt][3]));
        }
        tm0 = fmaxf(tm0, __shfl_xor_sync(0xffffffffu, tm0, 1));
        tm0 = fmaxf(tm0, __shfl_xor_sync(0xffffffffu, tm0, 2));
        tm1 = fmaxf(tm1, __shfl_xor_sync(0xffffffffu, tm1, 1));
        tm1 = fmaxf(tm1, __shfl_xor_sync(0xffffffffu, tm1, 2));

        float mn0 = fmaxf(m0, tm0), mn1 = fmaxf(m1, tm1);
        float al0 = __expf(m0 - mn0), al1 = __expf(m1 - mn1);
        m0 = mn0; m1 = mn1;

        unsigned plo[4], phi[4];
        float sum0 = 0.0f, sum1 = 0.0f;
#pragma unroll
        for (int nt = 0; nt < 4; nt++) {
            float p0 = __expf(s[nt][0] - mn0);
            float p1 = __expf(s[nt][1] - mn0);
            float p2 = __expf(s[nt][2] - mn1);
            float p3 = __expf(s[nt][3] - mn1);
            sum0 += p0 + p1;
            sum1 += p2 + p3;
            plo[nt] = packh2(p0, p1);
            phi[nt] = packh2(p2, p3);
        }
        sum0 += __shfl_xor_sync(0xffffffffu, sum0, 1);
        sum0 += __shfl_xor_sync(0xffffffffu, sum0, 2);
        sum1 += __shfl_xor_sync(0xffffffffu, sum1, 1);
        sum1 += __shfl_xor_sync(0xffffffffu, sum1, 2);
        l0 = l0 * al0 + sum0;
        l1 = l1 * al1 + sum1;

        if (__ballot_sync(0xffffffffu, (al0 != 1.0f) || (al1 != 1.0f))) {
#pragma unroll
            for (int nt = 0; nt < 16; nt++) {
                o[nt][0] *= al0; o[nt][1] *= al0;
                o[nt][2] *= al1; o[nt][3] *= al1;
            }
        }

#pragma unroll
        for (int ks = 0; ks < 2; ks++) {
            unsigned a0 = plo[2 * ks], a1 = phi[2 * ks];
            unsigned a2 = plo[2 * ks + 1], a3 = phi[2 * ks + 1];
#pragma unroll
            for (int nt = 0; nt < 16; nt++) {
                uint2 b = *(const uint2*)(Vbuf + (nt * 8 + g) * VT_LDH + ks * 16 + 4 * c);
                mma_f16(o[nt], a0, a1, a2, a3, b.x, b.y);
            }
        }
    }

    float inv0 = 1.0f / l0;
    float inv1 = 1.0f / l1;
    __half* out0 = attn + (size_t)row0 * HID + h * HD;
    __half* out1 = attn + (size_t)row1 * HID + h * HD;
#pragma unroll
    for (int nt = 0; nt < 16; nt++) {
        *(__half2*)(out0 + nt * 8 + 2 * c) = __floats2half2_rn(o[nt][0] * inv0, o[nt][1] * inv0);
        *(__half2*)(out1 + nt * 8 + 2 * c) = __floats2half2_rn(o[nt][2] * inv1, o[nt][3] * inv1);
    }

    // ---- tail: convert this CTA's slice of Wo to fp16 ----
    {
        const float4* src = (const float4*)Wo + (size_t)id * 8192;
        uint2* dst = (uint2*)wo16 + (size_t)id * 8192;
        for (int i = tid; i < 8192; i += 256) {
            float4 v = src[i];
            __half2 h0 = __floats2half2_rn(v.x, v.y);
            __half2 h1 = __floats2half2_rn(v.z, v.w);
            uint2 pk;
            pk.x = *(unsigned*)&h0;
            pk.y = *(unsigned*)&h1;
            dst[i] = pk;
        }
    }
}

// ---------------- launch ----------------
extern "C" void kernel_launch(void* const* d_in, const int* in_sizes, int n_in,
                              void* d_out, int out_size) {
    const float* hs   = (const float*)d_in[1];
    const float* Wqkv = (const float*)d_in[2];
    const float* bqkv = (const float*)d_in[3];
    const float* Wo   = (const float*)d_in[4];
    const float* bo   = (const float*)d_in[5];
    float* out = (float*)d_out;

    __half *attn16, *hs16, *wq16, *wo16, *qk16, *vT;
    float2* tab;
    cudaGetSymbolAddress((void**)&attn16, g_attn16);
    cudaGetSymbolAddress((void**)&hs16,   g_hs16);
    cudaGetSymbolAddress((void**)&wq16,   g_wq16);
    cudaGetSymbolAddress((void**)&wo16,   g_wo16);
    cudaGetSymbolAddress((void**)&qk16,   g_qk16);
    cudaGetSymbolAddress((void**)&vT,     g_vT);
    cudaGetSymbolAddress((void**)&tab,    g_tab);

    cudaFuncSetAttribute(flash_kernel, cudaFuncAttributeMaxDynamicSharedMemorySize,
                         FA_SMEM_BYTES);
    cudaFuncSetAttribute(gemm_qkv_fused, cudaFuncAttributeMaxDynamicSharedMemorySize,
                         GEMM_SMEM_BYTES);
    cudaFuncSetAttribute(gemm_f16_bias, cudaFuncAttributeMaxDynamicSharedMemorySize,
                         GEMM_SMEM_BYTES);

    // 0) merged pre-pass: cvt(Wqkv), cvt(hs), rope table
    pre_kernel<<<WQ_BLOCKS + HS_BLOCKS + TAB_BLOCKS, 256>>>(Wqkv, wq16, hs, hs16, tab);

    // 1) persistent QKV GEMM with fused epilogue
    gemm_qkv_fused<<<NPERS, 128, GEMM_SMEM_BYTES>>>(hs16, wq16, bqkv, qk16, vT, tab);

    // 2) fused flash attention, global heavy-first (+ Wo cvt in tail)
    flash_kernel<<<512, 256, FA_SMEM_BYTES>>>(qk16, vT, attn16, Wo, wo16);

    // 3) persistent O-projection GEMM
    gemm_f16_bias<<<NPERS, 128, GEMM_SMEM_BYTES>>>(attn16, wo16, bo, out, HID, HID);
}